// round 4
// baseline (speedup 1.0000x reference)
#include <cuda_runtime.h>

// ---------------------------------------------------------------------------
// GAT layer, algebraically folded:
//   c      = We^T @ a_e                      (64)      -> edge GEMM eliminated
//   z      = feats_node @ Wn^T               (20000x128)
//   s[i]   = z[i] . a_src,  t[i] = z[i] . a_dst
//   e_k    = lrelu(s[src_k] + t[dst_k] + feats_edge[k] . c)
//   m      = segment_max(e, dst)   (atomicMax on ordered-uint floats)
//   S      = segment_sum(exp(e-m[dst]), dst)
//   h[d]  += exp(e-m[d])/S[d] * z[src]       (float4 RED, z is L2-resident)
// ---------------------------------------------------------------------------

#define MAX_NODES 20000
#define MAX_EDGES 640000

__device__ __align__(16) float        g_z[MAX_NODES * 128];
__device__ float                      g_sn[MAX_NODES];
__device__ float                      g_tn[MAX_NODES];
__device__ __align__(16) float        g_c[64];
__device__ float                      g_e[MAX_EDGES];
__device__ unsigned int               g_m[MAX_NODES];
__device__ float                      g_ss[MAX_NODES];

__device__ __forceinline__ unsigned int enc_f(float f) {
    unsigned int u = __float_as_uint(f);
    return (u & 0x80000000u) ? ~u : (u | 0x80000000u);
}
__device__ __forceinline__ float dec_f(unsigned int u) {
    return (u & 0x80000000u) ? __uint_as_float(u ^ 0x80000000u)
                             : __uint_as_float(~u);
}

// -- prep: c = We^T a_e ; init m to enc(-inf), S to 0 ------------------------
__global__ void k_prep(const float* __restrict__ We,
                       const float* __restrict__ Wa, int n_nodes) {
    int t = blockIdx.x * blockDim.x + threadIdx.x;
    if (t < 64) {
        float acc = 0.f;
#pragma unroll 8
        for (int o = 0; o < 128; o++) acc += We[o * 64 + t] * Wa[256 + o];
        g_c[t] = acc;
    }
    if (t < n_nodes) {
        g_m[t] = 0x007FFFFFu;  // enc(-inf)
        g_ss[t] = 0.f;
    }
}

// -- z = A @ B^T, A [M,128], B [128,128], both K-contiguous ------------------
// classic 128x128x16 tile, 256 threads, TM=TN=8
__global__ __launch_bounds__(256) void k_gemm(const float* __restrict__ A,
                                              const float* __restrict__ B,
                                              int M) {
    __shared__ float As[16][132];
    __shared__ float Bs[16][132];
    const int tid = threadIdx.x;
    const int blockRow = blockIdx.x * 128;
    const int tr = tid >> 4;          // 0..15
    const int tc = tid & 15;          // 0..15
    const int lrow = tid >> 2;        // 0..63
    const int lcol = (tid & 3) * 4;   // 0,4,8,12

    float acc[8][8];
#pragma unroll
    for (int i = 0; i < 8; i++)
#pragma unroll
        for (int j = 0; j < 8; j++) acc[i][j] = 0.f;

    for (int kt = 0; kt < 128; kt += 16) {
#pragma unroll
        for (int h = 0; h < 2; h++) {
            int m = lrow + h * 64;
            int gm = blockRow + m;
            float4 v = (gm < M)
                           ? *(const float4*)&A[(size_t)gm * 128 + kt + lcol]
                           : make_float4(0.f, 0.f, 0.f, 0.f);
            As[lcol + 0][m] = v.x; As[lcol + 1][m] = v.y;
            As[lcol + 2][m] = v.z; As[lcol + 3][m] = v.w;
        }
#pragma unroll
        for (int h = 0; h < 2; h++) {
            int n = lrow + h * 64;
            float4 v = *(const float4*)&B[(size_t)n * 128 + kt + lcol];
            Bs[lcol + 0][n] = v.x; Bs[lcol + 1][n] = v.y;
            Bs[lcol + 2][n] = v.z; Bs[lcol + 3][n] = v.w;
        }
        __syncthreads();
#pragma unroll
        for (int k = 0; k < 16; k++) {
            float ra[8], rb[8];
#pragma unroll
            for (int i = 0; i < 8; i++) ra[i] = As[k][tr * 8 + i];
#pragma unroll
            for (int j = 0; j < 8; j++) rb[j] = Bs[k][tc * 8 + j];
#pragma unroll
            for (int i = 0; i < 8; i++)
#pragma unroll
                for (int j = 0; j < 8; j++) acc[i][j] += ra[i] * rb[j];
        }
        __syncthreads();
    }
#pragma unroll
    for (int i = 0; i < 8; i++) {
        int gm = blockRow + tr * 8 + i;
        if (gm < M) {
            float* out = &g_z[(size_t)gm * 128 + tc * 8];
            *(float4*)(out + 0) = make_float4(acc[i][0], acc[i][1], acc[i][2], acc[i][3]);
            *(float4*)(out + 4) = make_float4(acc[i][4], acc[i][5], acc[i][6], acc[i][7]);
        }
    }
}

// -- per-node s,t dots: one warp per node ------------------------------------
__global__ void k_nodedot(const float* __restrict__ Wa, int n_nodes) {
    int gw = (blockIdx.x * blockDim.x + threadIdx.x) >> 5;
    int lane = threadIdx.x & 31;
    if (gw >= n_nodes) return;
    float4 z4 = ((const float4*)g_z)[(size_t)gw * 32 + lane];
    float4 a4 = ((const float4*)Wa)[lane];         // a_src
    float4 b4 = ((const float4*)(Wa + 128))[lane]; // a_dst
    float s = z4.x * a4.x + z4.y * a4.y + z4.z * a4.z + z4.w * a4.w;
    float t = z4.x * b4.x + z4.y * b4.y + z4.z * b4.z + z4.w * b4.w;
#pragma unroll
    for (int o = 16; o > 0; o >>= 1) {
        s += __shfl_xor_sync(0xFFFFFFFFu, s, o);
        t += __shfl_xor_sync(0xFFFFFFFFu, t, o);
    }
    if (lane == 0) { g_sn[gw] = s; g_tn[gw] = t; }
}

// -- per-edge logit + leaky-relu + segment max: one warp per edge ------------
__global__ void k_edge_logit(const float* __restrict__ fe,
                             const int* __restrict__ src,
                             const int* __restrict__ dst, int n_edges) {
    int gw = (blockIdx.x * blockDim.x + threadIdx.x) >> 5;
    int lane = threadIdx.x & 31;
    if (gw >= n_edges) return;
    float2 f = ((const float2*)fe)[(size_t)gw * 32 + lane];
    float2 c = ((const float2*)g_c)[lane];
    float v = f.x * c.x + f.y * c.y;
#pragma unroll
    for (int o = 16; o > 0; o >>= 1) v += __shfl_xor_sync(0xFFFFFFFFu, v, o);
    if (lane == 0) {
        int s = src[gw], d = dst[gw];
        float logit = v + g_sn[s] + g_tn[d];
        float e = (logit > 0.f) ? logit : 0.2f * logit;
        g_e[gw] = e;
        atomicMax(&g_m[d], enc_f(e));
    }
}

// -- segment sum of exp(e - m[dst]) ------------------------------------------
__global__ void k_edge_sum(const int* __restrict__ dst, int n_edges) {
    int t = blockIdx.x * blockDim.x + threadIdx.x;
    if (t >= n_edges) return;
    int d = dst[t];
    float ex = __expf(g_e[t] - dec_f(g_m[d]));
    atomicAdd(&g_ss[d], ex);
}

// -- scatter h[dst] += alpha * z[src]: one warp per edge, float4 RED ---------
__global__ void k_scatter(const int* __restrict__ src,
                          const int* __restrict__ dst,
                          float* __restrict__ h, int n_edges) {
    int gw = (blockIdx.x * blockDim.x + threadIdx.x) >> 5;
    int lane = threadIdx.x & 31;
    if (gw >= n_edges) return;
    int d = dst[gw];
    float alpha;
    if (lane == 0) {
        float m = dec_f(g_m[d]);
        alpha = __expf(g_e[gw] - m) / g_ss[d];
    }
    alpha = __shfl_sync(0xFFFFFFFFu, alpha, 0);
    int s = src[gw];
    float4 z4 = ((const float4*)g_z)[(size_t)s * 32 + lane];
    float4 r = make_float4(z4.x * alpha, z4.y * alpha, z4.z * alpha, z4.w * alpha);
#if __CUDA_ARCH__ >= 900
    atomicAdd((float4*)&h[(size_t)d * 128 + lane * 4], r);
#else
    float* p = &h[(size_t)d * 128 + lane * 4];
    atomicAdd(p + 0, r.x); atomicAdd(p + 1, r.y);
    atomicAdd(p + 2, r.z); atomicAdd(p + 3, r.w);
#endif
}

extern "C" void kernel_launch(void* const* d_in, const int* in_sizes, int n_in,
                              void* d_out, int out_size) {
    const float* feats_node = (const float*)d_in[0];
    const float* feats_edge = (const float*)d_in[1];
    const float* Wn         = (const float*)d_in[2];
    const float* We         = (const float*)d_in[3];
    const float* Wa         = (const float*)d_in[4];
    const int*   src        = (const int*)d_in[5];
    const int*   dst        = (const int*)d_in[6];
    float*       h          = (float*)d_out;

    int n_nodes = in_sizes[0] / 128;
    int n_edges = in_sizes[5];

    cudaMemsetAsync(d_out, 0, (size_t)n_nodes * 128 * sizeof(float));
    k_prep<<<(n_nodes + 255) / 256, 256>>>(We, Wa, n_nodes);
    k_gemm<<<(n_nodes + 127) / 128, 256>>>(feats_node, Wn, n_nodes);
    k_nodedot<<<(n_nodes + 7) / 8, 256>>>(Wa, n_nodes);
    k_edge_logit<<<(n_edges + 7) / 8, 256>>>(feats_edge, src, dst, n_edges);
    k_edge_sum<<<(n_edges + 255) / 256, 256>>>(dst, n_edges);
    k_scatter<<<(n_edges + 7) / 8, 256>>>(src, dst, h, n_edges);
}

// round 5
// speedup vs baseline: 1.6115x; 1.6115x over previous
#include <cuda_runtime.h>

// ---------------------------------------------------------------------------
// GAT layer, folded + CSR softmax-aggregate:
//   c      = We^T @ a_e                       (edge GEMM eliminated)
//   z      = feats_node @ Wn^T
//   st[i]  = (z[i].a_src, z[i].a_dst)         packed float2
//   e_k    = lrelu(st[src].x + st[dst].y + feats_edge[k].c)   [8 edges/warp]
//   CSR by dst (hist fused into edge_logit, 1-block scan, build writes
//   e/src in CSR order) -> warp-per-node: max, sum-exp, h = sum alpha*z[src]
//   (deterministic-per-launch reduction, no REDs on h, no output memset)
// ---------------------------------------------------------------------------

#define MAX_NODES 20000
#define MAX_EDGES 640000

__device__ __align__(16) float  g_z[MAX_NODES * 128];
__device__ __align__(8)  float2 g_st[MAX_NODES];
__device__ __align__(16) float  g_c[64];
__device__ float                g_e[MAX_EDGES];
__device__ int                  g_cnt[MAX_NODES];
__device__ int                  g_off[MAX_NODES];
__device__ int                  g_cur[MAX_NODES];
__device__ float                g_ecsr[MAX_EDGES];
__device__ int                  g_scsr[MAX_EDGES];

// -- prep: c = We^T a_e ; zero histogram --------------------------------------
__global__ void k_prep(const float* __restrict__ We,
                       const float* __restrict__ Wa, int n_nodes) {
    int t = blockIdx.x * blockDim.x + threadIdx.x;
    if (t < 64) {
        float acc = 0.f;
#pragma unroll 8
        for (int o = 0; o < 128; o++) acc += We[o * 64 + t] * Wa[256 + o];
        g_c[t] = acc;
    }
    if (t < n_nodes) g_cnt[t] = 0;
}

// -- z = A @ B^T, A [M,128], B [128,128], both K-contiguous -------------------
__global__ __launch_bounds__(256) void k_gemm(const float* __restrict__ A,
                                              const float* __restrict__ B,
                                              int M) {
    __shared__ float As[16][132];
    __shared__ float Bs[16][132];
    const int tid = threadIdx.x;
    const int blockRow = blockIdx.x * 128;
    const int tr = tid >> 4;
    const int tc = tid & 15;
    const int lrow = tid >> 2;
    const int lcol = (tid & 3) * 4;

    float acc[8][8];
#pragma unroll
    for (int i = 0; i < 8; i++)
#pragma unroll
        for (int j = 0; j < 8; j++) acc[i][j] = 0.f;

    for (int kt = 0; kt < 128; kt += 16) {
#pragma unroll
        for (int h = 0; h < 2; h++) {
            int m = lrow + h * 64;
            int gm = blockRow + m;
            float4 v = (gm < M)
                           ? *(const float4*)&A[(size_t)gm * 128 + kt + lcol]
                           : make_float4(0.f, 0.f, 0.f, 0.f);
            As[lcol + 0][m] = v.x; As[lcol + 1][m] = v.y;
            As[lcol + 2][m] = v.z; As[lcol + 3][m] = v.w;
        }
#pragma unroll
        for (int h = 0; h < 2; h++) {
            int n = lrow + h * 64;
            float4 v = *(const float4*)&B[(size_t)n * 128 + kt + lcol];
            Bs[lcol + 0][n] = v.x; Bs[lcol + 1][n] = v.y;
            Bs[lcol + 2][n] = v.z; Bs[lcol + 3][n] = v.w;
        }
        __syncthreads();
#pragma unroll
        for (int k = 0; k < 16; k++) {
            float ra[8], rb[8];
#pragma unroll
            for (int i = 0; i < 8; i++) ra[i] = As[k][tr * 8 + i];
#pragma unroll
            for (int j = 0; j < 8; j++) rb[j] = Bs[k][tc * 8 + j];
#pragma unroll
            for (int i = 0; i < 8; i++)
#pragma unroll
                for (int j = 0; j < 8; j++) acc[i][j] += ra[i] * rb[j];
        }
        __syncthreads();
    }
#pragma unroll
    for (int i = 0; i < 8; i++) {
        int gm = blockRow + tr * 8 + i;
        if (gm < M) {
            float* out = &g_z[(size_t)gm * 128 + tc * 8];
            *(float4*)(out + 0) = make_float4(acc[i][0], acc[i][1], acc[i][2], acc[i][3]);
            *(float4*)(out + 4) = make_float4(acc[i][4], acc[i][5], acc[i][6], acc[i][7]);
        }
    }
}

// -- per-node (s,t) dots: warp per node, packed float2 ------------------------
__global__ void k_nodedot(const float* __restrict__ Wa, int n_nodes) {
    int gw = (blockIdx.x * blockDim.x + threadIdx.x) >> 5;
    int lane = threadIdx.x & 31;
    if (gw >= n_nodes) return;
    float4 z4 = ((const float4*)g_z)[(size_t)gw * 32 + lane];
    float4 a4 = ((const float4*)Wa)[lane];
    float4 b4 = ((const float4*)(Wa + 128))[lane];
    float s = z4.x * a4.x + z4.y * a4.y + z4.z * a4.z + z4.w * a4.w;
    float t = z4.x * b4.x + z4.y * b4.y + z4.z * b4.z + z4.w * b4.w;
#pragma unroll
    for (int o = 16; o > 0; o >>= 1) {
        s += __shfl_xor_sync(0xFFFFFFFFu, s, o);
        t += __shfl_xor_sync(0xFFFFFFFFu, t, o);
    }
    if (lane == 0) g_st[gw] = make_float2(s, t);
}

// -- edge logits: 8 edges per warp (lane covers 16 floats), fused histogram ---
__global__ __launch_bounds__(256) void k_edge_logit(const float* __restrict__ fe,
                                                    const int* __restrict__ src,
                                                    const int* __restrict__ dst,
                                                    int n_edges) {
    int w = (blockIdx.x * blockDim.x + threadIdx.x) >> 5;
    int lane = threadIdx.x & 31;
    if (w * 8 >= n_edges) return;
    int eid = w * 8 + (lane >> 2);   // lane group of 4 per edge
    int part = lane & 3;             // 16-float slice within the edge

    float v = 0.f;
    if (eid < n_edges) {
        const float4* p = (const float4*)fe + (size_t)w * 128 + lane * 4;
        float4 f0 = p[0], f1 = p[1], f2 = p[2], f3 = p[3];
        const float4* cp = (const float4*)g_c + part * 4;
        float4 c0 = __ldg(cp + 0), c1 = __ldg(cp + 1);
        float4 c2 = __ldg(cp + 2), c3 = __ldg(cp + 3);
        v = f0.x * c0.x + f0.y * c0.y + f0.z * c0.z + f0.w * c0.w
          + f1.x * c1.x + f1.y * c1.y + f1.z * c1.z + f1.w * c1.w
          + f2.x * c2.x + f2.y * c2.y + f2.z * c2.z + f2.w * c2.w
          + f3.x * c3.x + f3.y * c3.y + f3.z * c3.z + f3.w * c3.w;
    }
    v += __shfl_xor_sync(0xFFFFFFFFu, v, 1);
    v += __shfl_xor_sync(0xFFFFFFFFu, v, 2);
    if (part == 0 && eid < n_edges) {
        int s = src[eid], d = dst[eid];
        float2 sts = g_st[s];
        float2 std_ = g_st[d];
        float logit = v + sts.x + std_.y;
        float e = (logit > 0.f) ? logit : 0.2f * logit;
        g_e[eid] = e;
        atomicAdd(&g_cnt[d], 1);
    }
}

// -- exclusive scan of g_cnt -> g_off, g_cur (single block) -------------------
__global__ __launch_bounds__(1024) void k_scan(int n) {
    __shared__ int wsum[32];
    int tid = threadIdx.x;
    int lane = tid & 31, wid = tid >> 5;
    int C = (n + 1023) >> 10;
    int lo = tid * C;
    int hi = lo + C; if (hi > n) hi = n; if (lo > n) lo = n;
    int local = 0;
    for (int i = lo; i < hi; i++) local += g_cnt[i];
    int v = local;
#pragma unroll
    for (int o = 1; o < 32; o <<= 1) {
        int u = __shfl_up_sync(0xFFFFFFFFu, v, o);
        if (lane >= o) v += u;
    }
    if (lane == 31) wsum[wid] = v;
    __syncthreads();
    if (wid == 0) {
        int wv = wsum[lane];
#pragma unroll
        for (int o = 1; o < 32; o <<= 1) {
            int u = __shfl_up_sync(0xFFFFFFFFu, wv, o);
            if (lane >= o) wv += u;
        }
        wsum[lane] = wv;
    }
    __syncthreads();
    int run = v - local + (wid > 0 ? wsum[wid - 1] : 0);
    for (int i = lo; i < hi; i++) {
        g_off[i] = run;
        g_cur[i] = run;
        run += g_cnt[i];
    }
}

// -- build CSR-ordered e / src arrays -----------------------------------------
__global__ void k_build(const int* __restrict__ src,
                        const int* __restrict__ dst, int n_edges) {
    int i = blockIdx.x * blockDim.x + threadIdx.x;
    if (i >= n_edges) return;
    int d = dst[i];
    int pos = atomicAdd(&g_cur[d], 1);
    g_ecsr[pos] = g_e[i];
    g_scsr[pos] = src[i];
}

// -- warp per node: softmax + weighted aggregate, single coalesced store ------
__global__ __launch_bounds__(256) void k_aggregate(float* __restrict__ h,
                                                   int n_nodes) {
    int node = (blockIdx.x * blockDim.x + threadIdx.x) >> 5;
    int lane = threadIdx.x & 31;
    if (node >= n_nodes) return;
    int off = g_off[node];
    int deg = g_cnt[node];

    float m = -3.402823466e+38f;
    for (int j = lane; j < deg; j += 32) m = fmaxf(m, g_ecsr[off + j]);
#pragma unroll
    for (int o = 16; o > 0; o >>= 1)
        m = fmaxf(m, __shfl_xor_sync(0xFFFFFFFFu, m, o));

    float S = 0.f;
    for (int j = lane; j < deg; j += 32) S += __expf(g_ecsr[off + j] - m);
#pragma unroll
    for (int o = 16; o > 0; o >>= 1) S += __shfl_xor_sync(0xFFFFFFFFu, S, o);
    float rS = (deg > 0) ? (1.f / S) : 0.f;

    float4 acc = make_float4(0.f, 0.f, 0.f, 0.f);
    int j = 0;
    for (; j + 2 <= deg; j += 2) {
        float e0 = g_ecsr[off + j], e1 = g_ecsr[off + j + 1];
        int   s0 = g_scsr[off + j], s1 = g_scsr[off + j + 1];
        float4 z0 = *(const float4*)&g_z[(size_t)s0 * 128 + lane * 4];
        float4 z1 = *(const float4*)&g_z[(size_t)s1 * 128 + lane * 4];
        float a0 = __expf(e0 - m) * rS;
        float a1 = __expf(e1 - m) * rS;
        acc.x += a0 * z0.x + a1 * z1.x;
        acc.y += a0 * z0.y + a1 * z1.y;
        acc.z += a0 * z0.z + a1 * z1.z;
        acc.w += a0 * z0.w + a1 * z1.w;
    }
    if (j < deg) {
        float e0 = g_ecsr[off + j];
        int   s0 = g_scsr[off + j];
        float4 z0 = *(const float4*)&g_z[(size_t)s0 * 128 + lane * 4];
        float a0 = __expf(e0 - m) * rS;
        acc.x += a0 * z0.x; acc.y += a0 * z0.y;
        acc.z += a0 * z0.z; acc.w += a0 * z0.w;
    }
    *(float4*)&h[(size_t)node * 128 + lane * 4] = acc;
}

extern "C" void kernel_launch(void* const* d_in, const int* in_sizes, int n_in,
                              void* d_out, int out_size) {
    const float* feats_node = (const float*)d_in[0];
    const float* feats_edge = (const float*)d_in[1];
    const float* Wn         = (const float*)d_in[2];
    const float* We         = (const float*)d_in[3];
    const float* Wa         = (const float*)d_in[4];
    const int*   src        = (const int*)d_in[5];
    const int*   dst        = (const int*)d_in[6];
    float*       h          = (float*)d_out;

    int n_nodes = in_sizes[0] / 128;
    int n_edges = in_sizes[5];

    k_prep<<<(n_nodes + 255) / 256, 256>>>(We, Wa, n_nodes);
    k_gemm<<<(n_nodes + 127) / 128, 256>>>(feats_node, Wn, n_nodes);
    k_nodedot<<<(n_nodes + 7) / 8, 256>>>(Wa, n_nodes);
    int warps_el = (n_edges + 7) / 8;
    k_edge_logit<<<(warps_el + 7) / 8, 256>>>(feats_edge, src, dst, n_edges);
    k_scan<<<1, 1024>>>(n_nodes);
    k_build<<<(n_edges + 255) / 256, 256>>>(src, dst, n_edges);
    k_aggregate<<<(n_nodes + 7) / 8, 256>>>(h, n_nodes);
}